// round 10
// baseline (speedup 1.0000x reference)
#include <cuda_runtime.h>
#include <math.h>

// VMC walker simulation:
//   65536 walkers, 128 warmup + 384 measured Metropolis steps.
//   Streams noise[512][65536] and unif[512][65536] once (256 MiB).
//
// Output layout (14 float32): complex tuple (Es, Ds[3], EDs[3]) split into
// real-parts-then-imag-parts (validated in R8):
//   [0]      Es.re
//   [1..3]   Ds.re  = [0, mean(a^2), 2*th1*mean(a)]
//   [4..6]   EDs.re = [mean(e.im*r), mean(e.re*a^2), 2*th1*mean(e.re*a)]
//   [7]      Es.im
//   [8..10]  Ds.im  = [mean(r), 0, 0]
//   [11..13] EDs.im = [-mean(e.re*r), mean(e.im*a^2), 2*th1*mean(e.im*a)]

#define NUM_WALKERS 65536
#define NUM_WARMUP  128
#define NUM_STEPS   384
#define TOTAL_STEPS (NUM_WARMUP + NUM_STEPS)
#define NBLOCKS     1024
#define NTHREADS    64
#define NACC        8

// Per-block partials + completion counter (no allocations).
__device__ double       g_partial[NBLOCKS][NACC];
__device__ unsigned int g_count = 0;

__device__ __forceinline__ float ex2f(float x) {
    float y;
    asm("ex2.approx.ftz.f32 %0, %1;" : "=f"(y) : "f"(x));
    return y;
}

__global__ __launch_bounds__(NTHREADS)
void vmc_kernel(const float* __restrict__ theta,
                const float* __restrict__ r0,
                const float* __restrict__ s_dev_p,
                const float* __restrict__ noise,
                const float* __restrict__ unif,
                float* __restrict__ out)
{
    const int w = blockIdx.x * NTHREADS + threadIdx.x;   // walker id
    const float th0 = theta[0], th1 = theta[1], th2 = theta[2];
    const float sdev = s_dev_p[0];

    const float IL = 1.4426950408889634f;   // 1/ln(2)
    // Metropolis accept: log(u) < -2*th1*(ap^2 - a^2)
    //   <=> log2(u) < c1*(ap^2 - a^2),  c1 = -2*th1/ln2
    const float c1 = -2.0f * th1 * IL;
    // e-term: a = r - th2, A = exp(th1*(2a-1)) = 2^(c2*a - c3),
    //                       B = exp(-th1*(2a+1)) = 2^(-c2*a - c3)
    const float c2 = 2.0f * th1 * IL;
    const float c3 = th1 * IL;
    const float ncos0 = -cosf(th0);
    const float nsin0 = -sinf(th0);

    float r  = r0[w];
    float a  = r - th2;
    float a2 = a * a;

    const float* np = noise + w;
    const float* up = unif + w;

    // ---- warmup: Metropolis only ----
    #pragma unroll 8
    for (int t = 0; t < NUM_WARMUP; ++t) {
        float n = np[(size_t)t * NUM_WALKERS];
        float u = up[(size_t)t * NUM_WALKERS];
        float rp  = fmaf(sdev, n, r);
        float ap  = rp - th2;
        float ap2 = ap * ap;
        float lr  = c1 * (ap2 - a2);
        bool acc  = __log2f(u) < lr;
        r  = acc ? rp  : r;
        a2 = acc ? ap2 : a2;
    }
    a = r - th2;   // exact: matches the ap of the last accepted move

    float s_er = 0.f, s_ei = 0.f;           // sum e
    float s_r  = 0.f, s_a2 = 0.f;           // sum r, a^2
    float s_er_r  = 0.f, s_ei_r  = 0.f;     // sum e * r
    float s_er_a2 = 0.f, s_ei_a2 = 0.f;     // sum e * a^2

    // ---- measurement ----
    #pragma unroll 4
    for (int t = NUM_WARMUP; t < TOTAL_STEPS; ++t) {
        float n = np[(size_t)t * NUM_WALKERS];
        float u = up[(size_t)t * NUM_WALKERS];
        float rp  = fmaf(sdev, n, r);
        float ap  = rp - th2;
        float ap2 = ap * ap;
        float lr  = c1 * (ap2 - a2);
        bool acc  = __log2f(u) < lr;
        r  = acc ? rp  : r;
        a  = acc ? ap  : a;
        a2 = acc ? ap2 : a2;

        float x2 = c2 * a;
        float A  = ex2f(x2 - c3);
        float B  = ex2f(-x2 - c3);
        float e_re = ncos0 * (A + B);
        float e_im = nsin0 * (B - A);

        s_er += e_re;  s_ei += e_im;
        s_r  += r;     s_a2 += a2;
        s_er_r  = fmaf(e_re, r,  s_er_r);
        s_ei_r  = fmaf(e_im, r,  s_ei_r);
        s_er_a2 = fmaf(e_re, a2, s_er_a2);
        s_ei_a2 = fmaf(e_im, a2, s_ei_a2);
    }

    // ---- block reduction (2 warps, deterministic) ----
    float v[NACC] = { s_er, s_ei, s_r, s_a2,
                      s_er_r, s_ei_r, s_er_a2, s_ei_a2 };
    const int lane = threadIdx.x & 31;
    const int warp = threadIdx.x >> 5;

    #pragma unroll
    for (int k = 0; k < NACC; ++k) {
        #pragma unroll
        for (int o = 16; o > 0; o >>= 1)
            v[k] += __shfl_down_sync(0xffffffffu, v[k], o);
    }

    __shared__ float red[2][NACC];
    if (lane == 0) {
        #pragma unroll
        for (int k = 0; k < NACC; ++k) red[warp][k] = v[k];
    }
    __syncthreads();

    if (threadIdx.x == 0) {
        #pragma unroll
        for (int k = 0; k < NACC; ++k)
            g_partial[blockIdx.x][k] = (double)red[0][k] + (double)red[1][k];
    }

    // ---- last-block grid reduction ----
    __shared__ bool is_last;
    __threadfence();
    if (threadIdx.x == 0) {
        unsigned int c = atomicAdd(&g_count, 1u);
        is_last = (c == (unsigned int)(gridDim.x - 1));
    }
    __syncthreads();
    if (!is_last) return;

    __threadfence();
    __shared__ double S[NACC];
    if (threadIdx.x < 32) {
        #pragma unroll
        for (int k = 0; k < NACC; ++k) {
            double s = 0.0;
            for (int b = lane; b < NBLOCKS; b += 32)
                s += g_partial[b][k];
            #pragma unroll
            for (int o = 16; o > 0; o >>= 1)
                s += __shfl_down_sync(0xffffffffu, s, o);
            if (lane == 0) S[k] = s;
        }
    }
    __syncthreads();

    if (threadIdx.x == 0) {
        const double scale = 1.0 / ((double)NUM_WALKERS * (double)NUM_STEPS);
        const double dth1 = (double)th1;
        const double dth2 = (double)th2;
        double er   = S[0] * scale;   // mean e.re
        double ei   = S[1] * scale;   // mean e.im
        double mr   = S[2] * scale;   // mean r
        double ma2  = S[3] * scale;   // mean a^2
        double err_ = S[4] * scale;   // mean e.re * r
        double eir  = S[5] * scale;   // mean e.im * r
        double era2 = S[6] * scale;   // mean e.re * a^2
        double eia2 = S[7] * scale;   // mean e.im * a^2
        double ma   = mr   - dth2;            // mean a
        double era  = err_ - dth2 * er;       // mean e.re * a
        double eia  = eir  - dth2 * ei;       // mean e.im * a

        // real parts
        out[0]  = (float)er;
        out[1]  = 0.0f;
        out[2]  = (float)ma2;
        out[3]  = (float)(2.0 * dth1 * ma);
        out[4]  = (float)eir;
        out[5]  = (float)era2;
        out[6]  = (float)(2.0 * dth1 * era);
        // imag parts
        out[7]  = (float)ei;
        out[8]  = (float)mr;
        out[9]  = 0.0f;
        out[10] = 0.0f;
        out[11] = (float)(-err_);
        out[12] = (float)eia2;
        out[13] = (float)(2.0 * dth1 * eia);

        g_count = 0;   // reset for next graph replay
    }
}

extern "C" void kernel_launch(void* const* d_in, const int* in_sizes, int n_in,
                              void* d_out, int out_size)
{
    const float* theta = nullptr;
    const float* r0    = nullptr;
    const float* sdev  = nullptr;
    const float* noise = nullptr;
    const float* unif  = nullptr;
    const long long big = (long long)TOTAL_STEPS * NUM_WALKERS;
    for (int i = 0; i < n_in; ++i) {
        long long sz = in_sizes[i];
        if (sz == 3)                { theta = (const float*)d_in[i]; }
        else if (sz == 1)           { sdev  = (const float*)d_in[i]; }
        else if (sz == NUM_WALKERS) { r0    = (const float*)d_in[i]; }
        else if (sz == big) {
            if (!noise) noise = (const float*)d_in[i];
            else        unif  = (const float*)d_in[i];
        }
    }

    vmc_kernel<<<NBLOCKS, NTHREADS>>>(theta, r0, sdev, noise, unif,
                                      (float*)d_out);
}